// round 1
// baseline (speedup 1.0000x reference)
#include <cuda_runtime.h>
#include <cstdint>

#define DD 128
#define MAXN 50000

// Scratch (no cudaMalloc allowed): device globals.
__device__ float g_agg[MAXN * DD];
__device__ float g_h1[MAXN * DD];
__device__ float g_h2[MAXN * DD];
__device__ float g_deg[MAXN];
__device__ int   g_is64;

// ---------------------------------------------------------------------------
// Detect whether edge_index is int64 or int32 on device.
// If int64 (values < 50000), every odd 32-bit word is zero. For int32 data the
// odd words are random indices (nonzero with overwhelming probability).
// ---------------------------------------------------------------------------
__global__ void detect_kernel(const unsigned int* __restrict__ ei, int nwords) {
    __shared__ unsigned int s_or;
    if (threadIdx.x == 0) s_or = 0u;
    __syncthreads();
    unsigned int v = 0u;
    int idx = 2 * (int)threadIdx.x + 1;          // odd words
    if (idx < nwords) v = ei[idx];
    int idx2 = idx + 4096;
    if (idx2 < nwords) v |= ei[idx2];
    if (v) atomicOr(&s_or, v);
    __syncthreads();
    if (threadIdx.x == 0) g_is64 = (s_or == 0u) ? 1 : 0;
}

// ---------------------------------------------------------------------------
// Degree: one thread per edge, count into g_deg[dst]. (Run once; edges are
// identical across the 3 layers.)
// ---------------------------------------------------------------------------
__global__ void deg_kernel(const void* __restrict__ eidx, int E) {
    int e = blockIdx.x * blockDim.x + threadIdx.x;
    if (e >= E) return;
    int dst;
    if (g_is64) dst = (int)((const long long*)eidx)[E + e];
    else        dst = ((const int*)eidx)[E + e];
    atomicAdd(&g_deg[dst], 1.0f);
}

// ---------------------------------------------------------------------------
// Scatter: one warp per edge. Each lane moves a float4 of the 128-float row:
// gather X[src] (coalesced 512B) and vectorized reduction into agg[dst].
// ---------------------------------------------------------------------------
__global__ void scatter_kernel(const void* __restrict__ eidx,
                               const float* __restrict__ X,
                               float* __restrict__ agg, int E) {
    int warp = (int)((blockIdx.x * blockDim.x + threadIdx.x) >> 5);
    int lane = threadIdx.x & 31;
    if (warp >= E) return;
    long long src, dst;
    if (g_is64) {
        const long long* ei = (const long long*)eidx;
        src = ei[warp]; dst = ei[E + warp];
    } else {
        const int* ei = (const int*)eidx;
        src = ei[warp]; dst = ei[E + warp];
    }
    float4 v = *(const float4*)(X + src * DD + lane * 4);
    float* p = agg + dst * DD + lane * 4;
    asm volatile("red.global.add.v4.f32 [%0], {%1,%2,%3,%4};"
                 :: "l"(p), "f"(v.x), "f"(v.y), "f"(v.z), "f"(v.w) : "memory");
}

// ---------------------------------------------------------------------------
// Fused GEMM: Y = relu( (agg/max(deg,1)) @ Wl^T + bl + X @ Wr^T )
// Tile: 128 rows x 128 cols, K = 2 chunks of 128 (chunk0: mean/Wl, chunk1: X/Wr).
// 256 threads, 8x8 microtile per thread. A and W kept k-contiguous in smem
// (stride 132 floats), fragments strided by 16 so LDS.128 conflicts stay <=2-way.
// ---------------------------------------------------------------------------
#define LDS_ 132
#define GEMM_SMEM (2 * 128 * LDS_ * (int)sizeof(float))

__global__ void __launch_bounds__(256, 1)
gemm_fused(const float* __restrict__ agg, const float* __restrict__ deg,
           const float* __restrict__ X,
           const float* __restrict__ Wl, const float* __restrict__ bl,
           const float* __restrict__ Wr,
           float* __restrict__ Y, int M) {
    extern __shared__ float smem[];
    float* As = smem;              // [128][132]
    float* Ws = smem + 128 * LDS_; // [128][132]

    int tid = threadIdx.x;
    int tx = tid & 15;             // col group
    int ty = tid >> 4;             // row group
    int row0 = blockIdx.x << 7;

    float acc[8][8];
#pragma unroll
    for (int i = 0; i < 8; i++)
#pragma unroll
        for (int j = 0; j < 8; j++) acc[i][j] = 0.0f;

#pragma unroll
    for (int kc = 0; kc < 2; kc++) {
        const float* Ag = kc ? X  : agg;
        const float* Wg = kc ? Wr : Wl;

        // Load 128x128 A tile (apply 1/deg on chunk 0) and W tile.
#pragma unroll
        for (int it = 0; it < 16; it++) {
            int fid = tid + it * 256;        // float4 id 0..4095
            int r = fid >> 5;
            int c = (fid & 31) << 2;
            float4 v = make_float4(0.f, 0.f, 0.f, 0.f);
            int grow = row0 + r;
            if (grow < M) {
                v = *(const float4*)(Ag + (size_t)grow * DD + c);
                if (kc == 0) {
                    float s = 1.0f / fmaxf(deg[grow], 1.0f);
                    v.x *= s; v.y *= s; v.z *= s; v.w *= s;
                }
            }
            *(float4*)(As + r * LDS_ + c) = v;
            float4 w = *(const float4*)(Wg + (fid << 2));
            *(float4*)(Ws + r * LDS_ + c) = w;
        }
        __syncthreads();

#pragma unroll 2
        for (int k = 0; k < 128; k += 4) {
            float4 a[8], w[8];
#pragma unroll
            for (int i = 0; i < 8; i++)
                a[i] = *(const float4*)(As + (ty + 16 * i) * LDS_ + k);
#pragma unroll
            for (int j = 0; j < 8; j++)
                w[j] = *(const float4*)(Ws + (tx + 16 * j) * LDS_ + k);
#pragma unroll
            for (int i = 0; i < 8; i++)
#pragma unroll
                for (int j = 0; j < 8; j++) {
                    acc[i][j] += a[i].x * w[j].x;
                    acc[i][j] += a[i].y * w[j].y;
                    acc[i][j] += a[i].z * w[j].z;
                    acc[i][j] += a[i].w * w[j].w;
                }
        }
        __syncthreads();
    }

    // Epilogue: + bias, relu, store.
#pragma unroll
    for (int i = 0; i < 8; i++) {
        int r = row0 + ty + 16 * i;
        if (r >= M) continue;
#pragma unroll
        for (int j = 0; j < 8; j++) {
            int c = tx + 16 * j;
            Y[(size_t)r * DD + c] = fmaxf(acc[i][j] + bl[c], 0.0f);
        }
    }
}

// ---------------------------------------------------------------------------
// Launch
// ---------------------------------------------------------------------------
extern "C" void kernel_launch(void* const* d_in, const int* in_sizes, int n_in,
                              void* d_out, int out_size) {
    const float* x  = (const float*)d_in[0];
    const void*  ei = d_in[1];
    const float* Wl1 = (const float*)d_in[2];
    const float* bl1 = (const float*)d_in[3];
    const float* Wr1 = (const float*)d_in[4];
    const float* Wl2 = (const float*)d_in[5];
    const float* bl2 = (const float*)d_in[6];
    const float* Wr2 = (const float*)d_in[7];
    const float* Wl3 = (const float*)d_in[8];
    const float* bl3 = (const float*)d_in[9];
    const float* Wr3 = (const float*)d_in[10];
    float* out = (float*)d_out;

    int M = in_sizes[0] / DD;
    int E = in_sizes[1] / 2;

    float *agg, *h1, *h2, *deg;
    cudaGetSymbolAddress((void**)&agg, g_agg);
    cudaGetSymbolAddress((void**)&h1,  g_h1);
    cudaGetSymbolAddress((void**)&h2,  g_h2);
    cudaGetSymbolAddress((void**)&deg, g_deg);

    cudaFuncSetAttribute(gemm_fused, cudaFuncAttributeMaxDynamicSharedMemorySize,
                         GEMM_SMEM);

    // dtype detection (at least 2*E 32-bit words exist for either dtype)
    detect_kernel<<<1, 1024>>>((const unsigned int*)ei, 2 * E);

    // degrees (shared across layers)
    cudaMemsetAsync(deg, 0, (size_t)M * sizeof(float));
    deg_kernel<<<(E + 255) / 256, 256>>>(ei, E);

    int sc_blocks = (E * 32 + 255) / 256;
    int gm_blocks = (M + 127) / 128;

    const float* in = x;
    float* outs[3] = { h1, h2, out };
    const float* Wls[3] = { Wl1, Wl2, Wl3 };
    const float* bls[3] = { bl1, bl2, bl3 };
    const float* Wrs[3] = { Wr1, Wr2, Wr3 };

    for (int L = 0; L < 3; L++) {
        cudaMemsetAsync(agg, 0, (size_t)M * DD * sizeof(float));
        scatter_kernel<<<sc_blocks, 256>>>(ei, in, agg, E);
        gemm_fused<<<gm_blocks, 256, GEMM_SMEM>>>(agg, deg, in, Wls[L], bls[L],
                                                  Wrs[L], outs[L], M);
        in = outs[L];
    }
}

// round 4
// speedup vs baseline: 1.4741x; 1.4741x over previous
#include <cuda_runtime.h>
#include <cstdint>

#define DD 128
#define MAXN 50000

// Scratch (no cudaMalloc allowed): device globals.
__device__ float g_agg[MAXN * DD];
__device__ float g_h1[MAXN * DD];
__device__ float g_h2[MAXN * DD];
__device__ float g_deg[MAXN];
__device__ int   g_is64;

// ===========================================================================
// dtype detection (int64 vs int32 edge_index)
// ===========================================================================
__global__ void detect_kernel(const unsigned int* __restrict__ ei, int nwords) {
    __shared__ unsigned int s_or;
    if (threadIdx.x == 0) s_or = 0u;
    __syncthreads();
    unsigned int v = 0u;
    int idx = 2 * (int)threadIdx.x + 1;
    if (idx < nwords) v = ei[idx];
    int idx2 = idx + 4096;
    if (idx2 < nwords) v |= ei[idx2];
    if (v) atomicOr(&s_or, v);
    __syncthreads();
    if (threadIdx.x == 0) g_is64 = (s_or == 0u) ? 1 : 0;
}

__global__ void deg_kernel(const void* __restrict__ eidx, int E) {
    int e = blockIdx.x * blockDim.x + threadIdx.x;
    if (e >= E) return;
    int dst;
    if (g_is64) dst = (int)((const long long*)eidx)[E + e];
    else        dst = ((const int*)eidx)[E + e];
    atomicAdd(&g_deg[dst], 1.0f);
}

// ===========================================================================
// Scatter: one warp per edge, float4 per lane, red.global.add.v4.f32
// ===========================================================================
__global__ void scatter_kernel(const void* __restrict__ eidx,
                               const float* __restrict__ X,
                               float* __restrict__ agg, int E) {
    int warp = (int)((blockIdx.x * blockDim.x + threadIdx.x) >> 5);
    int lane = threadIdx.x & 31;
    if (warp >= E) return;
    long long src, dst;
    if (g_is64) {
        const long long* ei = (const long long*)eidx;
        src = ei[warp]; dst = ei[E + warp];
    } else {
        const int* ei = (const int*)eidx;
        src = ei[warp]; dst = ei[E + warp];
    }
    float4 v = *(const float4*)(X + src * DD + lane * 4);
    float* p = agg + dst * DD + lane * 4;
    asm volatile("red.global.add.v4.f32 [%0], {%1,%2,%3,%4};"
                 :: "l"(p), "f"(v.x), "f"(v.y), "f"(v.z), "f"(v.w) : "memory");
}

// ===========================================================================
// tf32 mma.sync fused GEMM:
//   Y = relu( (agg/max(deg,1)) @ Wl^T + bl + X @ Wr^T )
// CTA: 128 rows x 128 cols, K = 256 (8 chunks of 32). 8 warps as 4x2 grid,
// warp tile 32x64 via m16n8k8 (2 m-tiles x 8 n-tiles), fp32 accum.
//
// SMEM staging is pre-shuffled into mma fragment order:
//   A block (m-tile mb, k8-step ks): 128 floats; lane L's float4 at L*16 is
//     {A[g][t4], A[g+8][t4], A[g][t4+4], A[g+8][t4+4]}, g=L>>2, t4=L&3
//     (rows relative to mb*16, cols relative to ks*8)
//   B block (n-pair p, ks): lane L's float4 is
//     {W[p16+g][t4], W[p16+g][t4+4], W[p16+8+g][t4], W[p16+8+g][t4+4]}
//     = {b0,b1} of n-tile 2p and {b0,b1} of n-tile 2p+1.
// Blocks padded 512 -> 544 B to spread staging STS banks.
// ===========================================================================
#define BLKB   544
#define ACH    (32 * BLKB)          // 17408 bytes per chunk (A or B)
#define OFF_B  (2 * ACH)            // A double buffer first
#define GEMM_SMEM (4 * ACH)         // 69632 bytes

__device__ __forceinline__ float to_tf32(float x) {
    float r;
    asm("cvt.rna.tf32.f32 %0, %1;" : "=f"(r) : "f"(x));
    return r;
}

__device__ __forceinline__ void mma_tf32(float* c, const uint32_t* a,
                                         const uint32_t* b) {
    asm("mma.sync.aligned.m16n8k8.row.col.f32.tf32.tf32.f32 "
        "{%0,%1,%2,%3}, {%4,%5,%6,%7}, {%8,%9}, {%0,%1,%2,%3};"
        : "+f"(c[0]), "+f"(c[1]), "+f"(c[2]), "+f"(c[3])
        : "r"(a[0]), "r"(a[1]), "r"(a[2]), "r"(a[3]), "r"(b[0]), "r"(b[1]));
}

__device__ __forceinline__ void stage_chunk(
    char* smem, int buf, int chunk,
    const float* __restrict__ agg, const float* __restrict__ X,
    const float* __restrict__ Wl, const float* __restrict__ Wr,
    const float* __restrict__ deg, int row0, int M, int tid)
{
    const bool first = chunk < 4;
    const float* __restrict__ Ag = first ? agg : X;
    const float* __restrict__ Wg = first ? Wl : Wr;
    const int klocal = (chunk & 3) * 32;
    char* Ab = smem + buf * ACH;
    char* Bb = smem + OFF_B + buf * ACH;

#pragma unroll
    for (int i = 0; i < 4; i++) {
        int fid = tid + i * 256;        // 0..1023
        int row = fid >> 3;             // 0..127
        int c4  = fid & 7;              // k4 within 32-k chunk
        int ks  = c4 >> 1;
        int par = c4 & 1;               // k high half?

        // ---- A ----
        float4 v = make_float4(0.f, 0.f, 0.f, 0.f);
        int gr = row0 + row;
        if (gr < M) {
            v = *(const float4*)(Ag + (size_t)gr * DD + klocal + c4 * 4);
            if (first) {
                float s = 1.0f / fmaxf(deg[gr], 1.0f);
                v.x *= s; v.y *= s; v.z *= s; v.w *= s;
            }
        }
        int mb = row >> 4, rlo = row & 15;
        int g = rlo & 7, hi = rlo >> 3;
        int reg = hi + 2 * par;                       // a0/a1/a2/a3 slot
        char* abase = Ab + (mb * 4 + ks) * BLKB + g * 64 + reg * 4;
        *(float*)(abase +  0) = to_tf32(v.x);
        *(float*)(abase + 16) = to_tf32(v.y);
        *(float*)(abase + 32) = to_tf32(v.z);
        *(float*)(abase + 48) = to_tf32(v.w);

        // ---- B ---- (n = row; weights are full 128 rows, no guard)
        float4 w = *(const float4*)(Wg + (size_t)row * DD + klocal + c4 * 4);
        int p = row >> 4, nlo = row & 15;
        int g2 = nlo & 7, tile = nlo >> 3;
        int reg2 = tile * 2 + par;                    // {b0t0,b1t0,b0t1,b1t1}
        char* bbase = Bb + (p * 4 + ks) * BLKB + g2 * 64 + reg2 * 4;
        *(float*)(bbase +  0) = to_tf32(w.x);
        *(float*)(bbase + 16) = to_tf32(w.y);
        *(float*)(bbase + 32) = to_tf32(w.z);
        *(float*)(bbase + 48) = to_tf32(w.w);
    }
}

__global__ void __launch_bounds__(256, 2)
gemm_mma(const float* __restrict__ agg, const float* __restrict__ deg,
         const float* __restrict__ X,
         const float* __restrict__ Wl, const float* __restrict__ bl,
         const float* __restrict__ Wr,
         float* __restrict__ Y, int M)
{
    extern __shared__ char smem[];
    int tid = threadIdx.x;
    int lane = tid & 31;
    int wid = tid >> 5;
    int warp_m = wid & 3;     // row group of 32
    int warp_n = wid >> 2;    // col group of 64
    int row0 = blockIdx.x << 7;

    float acc[2][8][4];
#pragma unroll
    for (int mi = 0; mi < 2; mi++)
#pragma unroll
        for (int ni = 0; ni < 8; ni++)
#pragma unroll
            for (int r = 0; r < 4; r++) acc[mi][ni][r] = 0.0f;

    stage_chunk(smem, 0, 0, agg, X, Wl, Wr, deg, row0, M, tid);
    __syncthreads();

#pragma unroll
    for (int kc = 0; kc < 8; kc++) {
        int buf = kc & 1;
        if (kc + 1 < 8)
            stage_chunk(smem, buf ^ 1, kc + 1, agg, X, Wl, Wr, deg, row0, M, tid);

        char* Ab = smem + buf * ACH;
        char* Bb = smem + OFF_B + buf * ACH;
#pragma unroll
        for (int ks = 0; ks < 4; ks++) {
            uint32_t a[2][4], b[4][4];
#pragma unroll
            for (int mi = 0; mi < 2; mi++) {
                uint4 t = *(const uint4*)(Ab + ((warp_m * 2 + mi) * 4 + ks) * BLKB
                                          + lane * 16);
                a[mi][0] = t.x; a[mi][1] = t.y; a[mi][2] = t.z; a[mi][3] = t.w;
            }
#pragma unroll
            for (int pi = 0; pi < 4; pi++) {
                uint4 t = *(const uint4*)(Bb + ((warp_n * 4 + pi) * 4 + ks) * BLKB
                                          + lane * 16);
                b[pi][0] = t.x; b[pi][1] = t.y; b[pi][2] = t.z; b[pi][3] = t.w;
            }
#pragma unroll
            for (int mi = 0; mi < 2; mi++)
#pragma unroll
                for (int pi = 0; pi < 4; pi++) {
                    mma_tf32(acc[mi][pi * 2 + 0], a[mi], &b[pi][0]);
                    mma_tf32(acc[mi][pi * 2 + 1], a[mi], &b[pi][2]);
                }
        }
        __syncthreads();
    }

    // Epilogue: c0,c1 -> (row g, cols 2t4,2t4+1); c2,c3 -> row g+8.
    int g = lane >> 2, t4 = lane & 3;
#pragma unroll
    for (int mi = 0; mi < 2; mi++) {
        int r_lo = row0 + warp_m * 32 + mi * 16 + g;
        int r_hi = r_lo + 8;
#pragma unroll
        for (int ni = 0; ni < 8; ni++) {
            int col = warp_n * 64 + ni * 8 + t4 * 2;
            float b0 = __ldg(bl + col), b1 = __ldg(bl + col + 1);
            if (r_lo < M) {
                float2 o;
                o.x = fmaxf(acc[mi][ni][0] + b0, 0.f);
                o.y = fmaxf(acc[mi][ni][1] + b1, 0.f);
                *(float2*)(Y + (size_t)r_lo * DD + col) = o;
            }
            if (r_hi < M) {
                float2 o;
                o.x = fmaxf(acc[mi][ni][2] + b0, 0.f);
                o.y = fmaxf(acc[mi][ni][3] + b1, 0.f);
                *(float2*)(Y + (size_t)r_hi * DD + col) = o;
            }
        }
    }
}

// ===========================================================================
// Launch
// ===========================================================================
extern "C" void kernel_launch(void* const* d_in, const int* in_sizes, int n_in,
                              void* d_out, int out_size) {
    const float* x  = (const float*)d_in[0];
    const void*  ei = d_in[1];
    const float* Wl1 = (const float*)d_in[2];
    const float* bl1 = (const float*)d_in[3];
    const float* Wr1 = (const float*)d_in[4];
    const float* Wl2 = (const float*)d_in[5];
    const float* bl2 = (const float*)d_in[6];
    const float* Wr2 = (const float*)d_in[7];
    const float* Wl3 = (const float*)d_in[8];
    const float* bl3 = (const float*)d_in[9];
    const float* Wr3 = (const float*)d_in[10];
    float* out = (float*)d_out;

    int M = in_sizes[0] / DD;
    int E = in_sizes[1] / 2;

    float *agg, *h1, *h2, *deg;
    cudaGetSymbolAddress((void**)&agg, g_agg);
    cudaGetSymbolAddress((void**)&h1,  g_h1);
    cudaGetSymbolAddress((void**)&h2,  g_h2);
    cudaGetSymbolAddress((void**)&deg, g_deg);

    cudaFuncSetAttribute(gemm_mma, cudaFuncAttributeMaxDynamicSharedMemorySize,
                         GEMM_SMEM);

    detect_kernel<<<1, 1024>>>((const unsigned int*)ei, 2 * E);

    cudaMemsetAsync(deg, 0, (size_t)M * sizeof(float));
    deg_kernel<<<(E + 255) / 256, 256>>>(ei, E);

    int sc_blocks = (E * 32 + 255) / 256;
    int gm_blocks = (M + 127) / 128;

    const float* in = x;
    float* outs[3] = { h1, h2, out };
    const float* Wls[3] = { Wl1, Wl2, Wl3 };
    const float* bls[3] = { bl1, bl2, bl3 };
    const float* Wrs[3] = { Wr1, Wr2, Wr3 };

    for (int L = 0; L < 3; L++) {
        cudaMemsetAsync(agg, 0, (size_t)M * DD * sizeof(float));
        scatter_kernel<<<sc_blocks, 256>>>(ei, in, agg, E);
        gemm_mma<<<gm_blocks, 256, GEMM_SMEM>>>(agg, deg, in, Wls[L], bls[L],
                                                Wrs[L], outs[L], M);
        in = outs[L];
    }
}

// round 5
// speedup vs baseline: 1.8317x; 1.2426x over previous
#include <cuda_runtime.h>
#include <cstdint>

#define DD 128
#define MAXN 50000
#define MAXE 600000

// Scratch (no cudaMalloc allowed): device globals.
__device__ float g_agg[MAXN * DD];
__device__ float g_h1[MAXN * DD];
__device__ float g_h2[MAXN * DD];
__device__ int   g_cnt[MAXN];
__device__ int   g_off[MAXN + 1];
__device__ int   g_cur[MAXN];
__device__ int   g_srcl[MAXE];
__device__ int   g_is64;

// ===========================================================================
// dtype detection (int64 vs int32 edge_index)
// ===========================================================================
__global__ void detect_kernel(const unsigned int* __restrict__ ei, int nwords) {
    __shared__ unsigned int s_or;
    if (threadIdx.x == 0) s_or = 0u;
    __syncthreads();
    unsigned int v = 0u;
    int idx = 2 * (int)threadIdx.x + 1;
    if (idx < nwords) v = ei[idx];
    int idx2 = idx + 4096;
    if (idx2 < nwords) v |= ei[idx2];
    if (v) atomicOr(&s_or, v);
    __syncthreads();
    if (threadIdx.x == 0) g_is64 = (s_or == 0u) ? 1 : 0;
}

// ===========================================================================
// CSR build: histogram -> single-block scan -> atomic fill (once per call)
// ===========================================================================
__global__ void hist_kernel(const void* __restrict__ eidx, int E) {
    int e = blockIdx.x * blockDim.x + threadIdx.x;
    if (e >= E) return;
    int dst;
    if (g_is64) dst = (int)((const long long*)eidx)[E + e];
    else        dst = ((const int*)eidx)[E + e];
    atomicAdd(&g_cnt[dst], 1);
}

__global__ void scan_kernel(int M) {
    __shared__ int sums[1024];
    int t = threadIdx.x;
    int chunk = (M + 1023) >> 10;
    int lo = t * chunk;
    int hi = min(lo + chunk, M);
    int s = 0;
    for (int i = lo; i < hi; i++) s += g_cnt[i];
    sums[t] = s;
    __syncthreads();
    for (int d = 1; d < 1024; d <<= 1) {
        int o = (t >= d) ? sums[t - d] : 0;
        __syncthreads();
        sums[t] += o;
        __syncthreads();
    }
    int run = (t == 0) ? 0 : sums[t - 1];
    for (int i = lo; i < hi; i++) {
        g_off[i] = run;
        g_cur[i] = run;
        run += g_cnt[i];
    }
    if (t == 1023) g_off[M] = sums[1023];
}

__global__ void fill_kernel(const void* __restrict__ eidx, int E) {
    int e = blockIdx.x * blockDim.x + threadIdx.x;
    if (e >= E) return;
    int src, dst;
    if (g_is64) {
        const long long* ei = (const long long*)eidx;
        src = (int)ei[e]; dst = (int)ei[E + e];
    } else {
        const int* ei = (const int*)eidx;
        src = ei[e]; dst = ei[E + e];
    }
    int pos = atomicAdd(&g_cur[dst], 1);
    g_srcl[pos] = src;
}

// ===========================================================================
// Aggregation: one warp per node; gather neighbor rows, mean, store once.
// ===========================================================================
__global__ void __launch_bounds__(256)
agg_kernel(const float* __restrict__ X, float* __restrict__ agg, int M) {
    int node = (int)((blockIdx.x * blockDim.x + threadIdx.x) >> 5);
    int lane = threadIdx.x & 31;
    if (node >= M) return;
    int s = g_off[node], e = g_off[node + 1];

    float4 v0 = make_float4(0.f, 0.f, 0.f, 0.f);
    float4 v1 = make_float4(0.f, 0.f, 0.f, 0.f);
    for (int base = s; base < e; base += 32) {
        int mysrc = (base + lane < e) ? g_srcl[base + lane] : 0;
        int n = min(32, e - base);
        int j = 0;
        for (; j + 1 < n; j += 2) {
            int s0 = __shfl_sync(0xffffffffu, mysrc, j);
            int s1 = __shfl_sync(0xffffffffu, mysrc, j + 1);
            float4 t0 = *(const float4*)(X + (size_t)s0 * DD + lane * 4);
            float4 t1 = *(const float4*)(X + (size_t)s1 * DD + lane * 4);
            v0.x += t0.x; v0.y += t0.y; v0.z += t0.z; v0.w += t0.w;
            v1.x += t1.x; v1.y += t1.y; v1.z += t1.z; v1.w += t1.w;
        }
        if (j < n) {
            int s0 = __shfl_sync(0xffffffffu, mysrc, j);
            float4 t0 = *(const float4*)(X + (size_t)s0 * DD + lane * 4);
            v0.x += t0.x; v0.y += t0.y; v0.z += t0.z; v0.w += t0.w;
        }
    }
    float inv = 1.0f / fmaxf((float)(e - s), 1.0f);
    float4 o;
    o.x = (v0.x + v1.x) * inv;
    o.y = (v0.y + v1.y) * inv;
    o.z = (v0.z + v1.z) * inv;
    o.w = (v0.w + v1.w) * inv;
    *(float4*)(agg + (size_t)node * DD + lane * 4) = o;
}

// ===========================================================================
// tf32 mma.sync fused GEMM:
//   Y = relu( mean @ Wl^T + bl + X @ Wr^T )
// CTA: 128 rows x 128 cols, K = 256 (8 chunks of 32). 8 warps as 4x2 grid,
// warp tile 32x64 via m16n8k8 (2 m-tiles x 8 n-tiles), fp32 accum.
// SMEM staging pre-shuffled into mma fragment order (see R4 notes).
// ===========================================================================
#define BLKB   544
#define ACH    (32 * BLKB)
#define OFF_B  (2 * ACH)
#define GEMM_SMEM (4 * ACH)

__device__ __forceinline__ float to_tf32(float x) {
    float r;
    asm("cvt.rna.tf32.f32 %0, %1;" : "=f"(r) : "f"(x));
    return r;
}

__device__ __forceinline__ void mma_tf32(float* c, const uint32_t* a,
                                         const uint32_t* b) {
    asm("mma.sync.aligned.m16n8k8.row.col.f32.tf32.tf32.f32 "
        "{%0,%1,%2,%3}, {%4,%5,%6,%7}, {%8,%9}, {%0,%1,%2,%3};"
        : "+f"(c[0]), "+f"(c[1]), "+f"(c[2]), "+f"(c[3])
        : "r"(a[0]), "r"(a[1]), "r"(a[2]), "r"(a[3]), "r"(b[0]), "r"(b[1]));
}

__device__ __forceinline__ void stage_chunk(
    char* smem, int buf, int chunk,
    const float* __restrict__ agg, const float* __restrict__ X,
    const float* __restrict__ Wl, const float* __restrict__ Wr,
    int row0, int M, int tid)
{
    const bool first = chunk < 4;
    const float* __restrict__ Ag = first ? agg : X;
    const float* __restrict__ Wg = first ? Wl : Wr;
    const int klocal = (chunk & 3) * 32;
    char* Ab = smem + buf * ACH;
    char* Bb = smem + OFF_B + buf * ACH;

#pragma unroll
    for (int i = 0; i < 4; i++) {
        int fid = tid + i * 256;
        int row = fid >> 3;
        int c4  = fid & 7;
        int ks  = c4 >> 1;
        int par = c4 & 1;

        // ---- A ----
        float4 v = make_float4(0.f, 0.f, 0.f, 0.f);
        int gr = row0 + row;
        if (gr < M)
            v = *(const float4*)(Ag + (size_t)gr * DD + klocal + c4 * 4);
        int mb = row >> 4, rlo = row & 15;
        int g = rlo & 7, hi = rlo >> 3;
        int reg = hi + 2 * par;
        char* abase = Ab + (mb * 4 + ks) * BLKB + g * 64 + reg * 4;
        *(float*)(abase +  0) = to_tf32(v.x);
        *(float*)(abase + 16) = to_tf32(v.y);
        *(float*)(abase + 32) = to_tf32(v.z);
        *(float*)(abase + 48) = to_tf32(v.w);

        // ---- B ----
        float4 w = *(const float4*)(Wg + (size_t)row * DD + klocal + c4 * 4);
        int p = row >> 4, nlo = row & 15;
        int g2 = nlo & 7, tile = nlo >> 3;
        int reg2 = tile * 2 + par;
        char* bbase = Bb + (p * 4 + ks) * BLKB + g2 * 64 + reg2 * 4;
        *(float*)(bbase +  0) = to_tf32(w.x);
        *(float*)(bbase + 16) = to_tf32(w.y);
        *(float*)(bbase + 32) = to_tf32(w.z);
        *(float*)(bbase + 48) = to_tf32(w.w);
    }
}

__global__ void __launch_bounds__(256, 2)
gemm_mma(const float* __restrict__ agg, const float* __restrict__ X,
         const float* __restrict__ Wl, const float* __restrict__ bl,
         const float* __restrict__ Wr,
         float* __restrict__ Y, int M)
{
    extern __shared__ char smem[];
    int tid = threadIdx.x;
    int lane = tid & 31;
    int wid = tid >> 5;
    int warp_m = wid & 3;
    int warp_n = wid >> 2;
    int row0 = blockIdx.x << 7;

    float acc[2][8][4];
#pragma unroll
    for (int mi = 0; mi < 2; mi++)
#pragma unroll
        for (int ni = 0; ni < 8; ni++)
#pragma unroll
            for (int r = 0; r < 4; r++) acc[mi][ni][r] = 0.0f;

    stage_chunk(smem, 0, 0, agg, X, Wl, Wr, row0, M, tid);
    __syncthreads();

#pragma unroll
    for (int kc = 0; kc < 8; kc++) {
        int buf = kc & 1;
        if (kc + 1 < 8)
            stage_chunk(smem, buf ^ 1, kc + 1, agg, X, Wl, Wr, row0, M, tid);

        char* Ab = smem + buf * ACH;
        char* Bb = smem + OFF_B + buf * ACH;
#pragma unroll
        for (int ks = 0; ks < 4; ks++) {
            uint32_t a[2][4], b[4][4];
#pragma unroll
            for (int mi = 0; mi < 2; mi++) {
                uint4 t = *(const uint4*)(Ab + ((warp_m * 2 + mi) * 4 + ks) * BLKB
                                          + lane * 16);
                a[mi][0] = t.x; a[mi][1] = t.y; a[mi][2] = t.z; a[mi][3] = t.w;
            }
#pragma unroll
            for (int pi = 0; pi < 4; pi++) {
                uint4 t = *(const uint4*)(Bb + ((warp_n * 4 + pi) * 4 + ks) * BLKB
                                          + lane * 16);
                b[pi][0] = t.x; b[pi][1] = t.y; b[pi][2] = t.z; b[pi][3] = t.w;
            }
#pragma unroll
            for (int mi = 0; mi < 2; mi++)
#pragma unroll
                for (int pi = 0; pi < 4; pi++) {
                    mma_tf32(acc[mi][pi * 2 + 0], a[mi], &b[pi][0]);
                    mma_tf32(acc[mi][pi * 2 + 1], a[mi], &b[pi][2]);
                }
        }
        __syncthreads();
    }

    int g = lane >> 2, t4 = lane & 3;
#pragma unroll
    for (int mi = 0; mi < 2; mi++) {
        int r_lo = row0 + warp_m * 32 + mi * 16 + g;
        int r_hi = r_lo + 8;
#pragma unroll
        for (int ni = 0; ni < 8; ni++) {
            int col = warp_n * 64 + ni * 8 + t4 * 2;
            float b0 = __ldg(bl + col), b1 = __ldg(bl + col + 1);
            if (r_lo < M) {
                float2 o;
                o.x = fmaxf(acc[mi][ni][0] + b0, 0.f);
                o.y = fmaxf(acc[mi][ni][1] + b1, 0.f);
                *(float2*)(Y + (size_t)r_lo * DD + col) = o;
            }
            if (r_hi < M) {
                float2 o;
                o.x = fmaxf(acc[mi][ni][2] + b0, 0.f);
                o.y = fmaxf(acc[mi][ni][3] + b1, 0.f);
                *(float2*)(Y + (size_t)r_hi * DD + col) = o;
            }
        }
    }
}

// ===========================================================================
// Launch
// ===========================================================================
extern "C" void kernel_launch(void* const* d_in, const int* in_sizes, int n_in,
                              void* d_out, int out_size) {
    const float* x  = (const float*)d_in[0];
    const void*  ei = d_in[1];
    const float* Wl1 = (const float*)d_in[2];
    const float* bl1 = (const float*)d_in[3];
    const float* Wr1 = (const float*)d_in[4];
    const float* Wl2 = (const float*)d_in[5];
    const float* bl2 = (const float*)d_in[6];
    const float* Wr2 = (const float*)d_in[7];
    const float* Wl3 = (const float*)d_in[8];
    const float* bl3 = (const float*)d_in[9];
    const float* Wr3 = (const float*)d_in[10];
    float* out = (float*)d_out;

    int M = in_sizes[0] / DD;
    int E = in_sizes[1] / 2;

    float *agg, *h1, *h2;
    int *cnt;
    cudaGetSymbolAddress((void**)&agg, g_agg);
    cudaGetSymbolAddress((void**)&h1,  g_h1);
    cudaGetSymbolAddress((void**)&h2,  g_h2);
    cudaGetSymbolAddress((void**)&cnt, g_cnt);

    cudaFuncSetAttribute(gemm_mma, cudaFuncAttributeMaxDynamicSharedMemorySize,
                         GEMM_SMEM);

    detect_kernel<<<1, 1024>>>((const unsigned int*)ei, 2 * E);

    // CSR build (once per call; reused by all 3 layers)
    cudaMemsetAsync(cnt, 0, (size_t)M * sizeof(int));
    hist_kernel<<<(E + 255) / 256, 256>>>(ei, E);
    scan_kernel<<<1, 1024>>>(M);
    fill_kernel<<<(E + 255) / 256, 256>>>(ei, E);

    int ag_blocks = (M * 32 + 255) / 256;
    int gm_blocks = (M + 127) / 128;

    const float* in = x;
    float* outs[3] = { h1, h2, out };
    const float* Wls[3] = { Wl1, Wl2, Wl3 };
    const float* bls[3] = { bl1, bl2, bl3 };
    const float* Wrs[3] = { Wr1, Wr2, Wr3 };

    for (int L = 0; L < 3; L++) {
        agg_kernel<<<ag_blocks, 256>>>(in, agg, M);
        gemm_mma<<<gm_blocks, 256, GEMM_SMEM>>>(agg, in, Wls[L], bls[L],
                                                Wrs[L], outs[L], M);
        in = outs[L];
    }
}

// round 6
// speedup vs baseline: 2.1445x; 1.1707x over previous
#include <cuda_runtime.h>
#include <cstdint>

#define DD 128
#define MAXN 50000
#define MAXE 600000

// Scratch (no cudaMalloc allowed): device globals.
__device__ float g_agg[MAXN * DD];
__device__ float g_h1[MAXN * DD];
__device__ float g_h2[MAXN * DD];
__device__ float g_Bpre[3 * 8 * 4096];   // per layer: 8 chunks x 4096 floats (swizzled tf32 Wl||Wr)
__device__ int   g_cnt[MAXN];
__device__ int   g_off[MAXN + 1];
__device__ int   g_cur[MAXN];
__device__ int   g_srcl[MAXE];
__device__ int   g_is64;

__device__ __forceinline__ uint32_t sw128(uint32_t off) {
    return off ^ ((off >> 3) & 0x70);
}

__device__ __forceinline__ float to_tf32(float x) {
    float r;
    asm("cvt.rna.tf32.f32 %0, %1;" : "=f"(r) : "f"(x));
    return r;
}

// ===========================================================================
// dtype detection (int64 vs int32 edge_index)
// ===========================================================================
__global__ void detect_kernel(const unsigned int* __restrict__ ei, int nwords) {
    __shared__ unsigned int s_or;
    if (threadIdx.x == 0) s_or = 0u;
    __syncthreads();
    unsigned int v = 0u;
    int idx = 2 * (int)threadIdx.x + 1;
    if (idx < nwords) v = ei[idx];
    int idx2 = idx + 4096;
    if (idx2 < nwords) v |= ei[idx2];
    if (v) atomicOr(&s_or, v);
    __syncthreads();
    if (threadIdx.x == 0) g_is64 = (s_or == 0u) ? 1 : 0;
}

// ===========================================================================
// CSR build: histogram -> single-block scan -> atomic fill (once per call)
// ===========================================================================
__global__ void hist_kernel(const void* __restrict__ eidx, int E) {
    int e = blockIdx.x * blockDim.x + threadIdx.x;
    if (e >= E) return;
    int dst;
    if (g_is64) dst = (int)((const long long*)eidx)[E + e];
    else        dst = ((const int*)eidx)[E + e];
    atomicAdd(&g_cnt[dst], 1);
}

__global__ void scan_kernel(int M) {
    __shared__ int sums[1024];
    int t = threadIdx.x;
    int chunk = (M + 1023) >> 10;
    int lo = t * chunk;
    int hi = min(lo + chunk, M);
    int s = 0;
    for (int i = lo; i < hi; i++) s += g_cnt[i];
    sums[t] = s;
    __syncthreads();
    for (int d = 1; d < 1024; d <<= 1) {
        int o = (t >= d) ? sums[t - d] : 0;
        __syncthreads();
        sums[t] += o;
        __syncthreads();
    }
    int run = (t == 0) ? 0 : sums[t - 1];
    for (int i = lo; i < hi; i++) {
        g_off[i] = run;
        g_cur[i] = run;
        run += g_cnt[i];
    }
    if (t == 1023) g_off[M] = sums[1023];
}

__global__ void fill_kernel(const void* __restrict__ eidx, int E) {
    int e = blockIdx.x * blockDim.x + threadIdx.x;
    if (e >= E) return;
    int src, dst;
    if (g_is64) {
        const long long* ei = (const long long*)eidx;
        src = (int)ei[e]; dst = (int)ei[E + e];
    } else {
        const int* ei = (const int*)eidx;
        src = ei[e]; dst = ei[E + e];
    }
    int pos = atomicAdd(&g_cur[dst], 1);
    g_srcl[pos] = src;
}

// ===========================================================================
// Aggregation: one warp per node; gather neighbor rows, mean, store once.
// ===========================================================================
__global__ void __launch_bounds__(256)
agg_kernel(const float* __restrict__ X, float* __restrict__ agg, int M) {
    int node = (int)((blockIdx.x * blockDim.x + threadIdx.x) >> 5);
    int lane = threadIdx.x & 31;
    if (node >= M) return;
    int s = g_off[node], e = g_off[node + 1];

    float4 v0 = make_float4(0.f, 0.f, 0.f, 0.f);
    float4 v1 = make_float4(0.f, 0.f, 0.f, 0.f);
    for (int base = s; base < e; base += 32) {
        int mysrc = (base + lane < e) ? g_srcl[base + lane] : 0;
        int n = min(32, e - base);
        int j = 0;
        for (; j + 1 < n; j += 2) {
            int s0 = __shfl_sync(0xffffffffu, mysrc, j);
            int s1 = __shfl_sync(0xffffffffu, mysrc, j + 1);
            float4 t0 = *(const float4*)(X + (size_t)s0 * DD + lane * 4);
            float4 t1 = *(const float4*)(X + (size_t)s1 * DD + lane * 4);
            v0.x += t0.x; v0.y += t0.y; v0.z += t0.z; v0.w += t0.w;
            v1.x += t1.x; v1.y += t1.y; v1.z += t1.z; v1.w += t1.w;
        }
        if (j < n) {
            int s0 = __shfl_sync(0xffffffffu, mysrc, j);
            float4 t0 = *(const float4*)(X + (size_t)s0 * DD + lane * 4);
            v0.x += t0.x; v0.y += t0.y; v0.z += t0.z; v0.w += t0.w;
        }
    }
    float inv = 1.0f / fmaxf((float)(e - s), 1.0f);
    float4 o;
    o.x = (v0.x + v1.x) * inv;
    o.y = (v0.y + v1.y) * inv;
    o.z = (v0.z + v1.z) * inv;
    o.w = (v0.w + v1.w) * inv;
    *(float4*)(agg + (size_t)node * DD + lane * 4) = o;
}

// ===========================================================================
// Weight pre-conversion: per layer, build swizzled chunk-major tf32 image of
// Wl (chunks 0-3) || Wr (chunks 4-7). Layout per chunk: 128 rows x 32 floats
// (128B rows), SW128 XOR swizzle baked in so GEMM can cp.async linearly.
// ===========================================================================
__global__ void prep_B(const float* __restrict__ Wl1, const float* __restrict__ Wr1,
                       const float* __restrict__ Wl2, const float* __restrict__ Wr2,
                       const float* __restrict__ Wl3, const float* __restrict__ Wr3) {
    int t = blockIdx.x * blockDim.x + threadIdx.x;   // 0..24575
    int layer = t >> 13;
    int rem = t & 8191;
    int chunk = rem >> 10;
    int fid = rem & 1023;
    const float* W;
    if (layer == 0) W = (chunk < 4) ? Wl1 : Wr1;
    else if (layer == 1) W = (chunk < 4) ? Wl2 : Wr2;
    else W = (chunk < 4) ? Wl3 : Wr3;
    int row = fid >> 3, c4 = fid & 7;
    float4 v = *(const float4*)(W + row * DD + (chunk & 3) * 32 + c4 * 4);
    v.x = to_tf32(v.x); v.y = to_tf32(v.y); v.z = to_tf32(v.z); v.w = to_tf32(v.w);
    uint32_t dst = (uint32_t)layer * 32768 + (uint32_t)chunk * 4096
                 + (sw128(row * 128 + c4 * 16) >> 2);
    *(float4*)(g_Bpre + dst) = v;
}

// ===========================================================================
// tf32 mma.sync fused GEMM with ldmatrix + cp.async(B) + reg-prefetch(A):
//   Y = relu( mean @ Wl^T + bl + X @ Wr^T )
// CTA 128x128, K=256 as 8 chunks of 32. SMEM: A/B double buffers, plain
// K-major 128B rows with SW128 swizzle. 8 warps 4x2, warp tile 32x64.
// ===========================================================================
#define CHK 16384
#define GEMM_SMEM (4 * CHK)    // A0,A1,B0,B1

__device__ __forceinline__ uint32_t smem_u32(const void* p) {
    uint32_t a;
    asm("{ .reg .u64 t; cvta.to.shared.u64 t, %1; cvt.u32.u64 %0, t; }"
        : "=r"(a) : "l"(p));
    return a;
}

__device__ __forceinline__ void ldsm4(uint32_t* r, uint32_t addr) {
    asm volatile("ldmatrix.sync.aligned.m8n8.x4.shared.b16 {%0,%1,%2,%3}, [%4];"
                 : "=r"(r[0]), "=r"(r[1]), "=r"(r[2]), "=r"(r[3]) : "r"(addr));
}

__device__ __forceinline__ void mma_tf32(float* c, const uint32_t* a,
                                         const uint32_t* b) {
    asm("mma.sync.aligned.m16n8k8.row.col.f32.tf32.tf32.f32 "
        "{%0,%1,%2,%3}, {%4,%5,%6,%7}, {%8,%9}, {%0,%1,%2,%3};"
        : "+f"(c[0]), "+f"(c[1]), "+f"(c[2]), "+f"(c[3])
        : "r"(a[0]), "r"(a[1]), "r"(a[2]), "r"(a[3]), "r"(b[0]), "r"(b[1]));
}

__device__ __forceinline__ void cp16(uint32_t dst, const void* src) {
    asm volatile("cp.async.cg.shared.global [%0], [%1], 16;"
                 :: "r"(dst), "l"(src) : "memory");
}

__global__ void __launch_bounds__(256, 2)
gemm_mma(const float* __restrict__ agg, const float* __restrict__ X,
         const float* __restrict__ Bpre, const float* __restrict__ bl,
         float* __restrict__ Y, int M)
{
    extern __shared__ char smem[];
    uint32_t sbase = smem_u32(smem);
    int tid = threadIdx.x;
    int lane = tid & 31;
    int wid = tid >> 5;
    int warp_m = wid & 3;
    int warp_n = wid >> 2;
    int row0 = blockIdx.x << 7;

    // staging geometry for this thread (4 float4s per chunk)
    int st_row[4], st_c4[4];
    uint32_t st_sw[4];
#pragma unroll
    for (int i = 0; i < 4; i++) {
        int fid = tid + i * 256;
        st_row[i] = fid >> 3;
        st_c4[i]  = fid & 7;
        st_sw[i]  = sw128(st_row[i] * 128 + st_c4[i] * 16);
    }

    float acc[2][8][4];
#pragma unroll
    for (int mi = 0; mi < 2; mi++)
#pragma unroll
        for (int ni = 0; ni < 8; ni++)
#pragma unroll
            for (int r = 0; r < 4; r++) acc[mi][ni][r] = 0.0f;

    // ldmatrix per-lane address components
    int lane15 = lane & 15;
    uint32_t aseg = (lane >> 4) * 16;
    int arow = warp_m * 32 + lane15;
    uint32_t aswz = (arow & 7) * 16;
    uint32_t aoff = (uint32_t)arow * 128;

    uint32_t bseg = ((lane >> 3) & 1) * 16;
    int brow = warp_n * 64 + ((lane >> 4) * 8) + (lane & 7);
    uint32_t bswz = (brow & 7) * 16;
    uint32_t boff = (uint32_t)brow * 128;

    // ---- prologue: chunk 0 ----
    {
#pragma unroll
        for (int i = 0; i < 4; i++)
            cp16(sbase + 2 * CHK + (uint32_t)(tid + i * 256) * 16,
                 Bpre + (tid + i * 256) * 4);
        asm volatile("cp.async.commit_group;" ::: "memory");
#pragma unroll
        for (int i = 0; i < 4; i++) {
            int gr = row0 + st_row[i];
            float4 v = make_float4(0.f, 0.f, 0.f, 0.f);
            if (gr < M) v = *(const float4*)(agg + (size_t)gr * DD + st_c4[i] * 4);
            v.x = to_tf32(v.x); v.y = to_tf32(v.y);
            v.z = to_tf32(v.z); v.w = to_tf32(v.w);
            *(float4*)(smem + st_sw[i]) = v;
        }
        asm volatile("cp.async.wait_group 0;" ::: "memory");
        __syncthreads();
    }

#pragma unroll
    for (int kc = 0; kc < 8; kc++) {
        int cur = kc & 1;
        int nxt = cur ^ 1;
        float4 va[4];
        const bool haven = (kc + 1) < 8;
        if (haven) {
            // B chunk kc+1 via cp.async (pre-swizzled gmem image, linear copy)
            const float* bsrc = Bpre + (kc + 1) * 4096;
#pragma unroll
            for (int i = 0; i < 4; i++)
                cp16(sbase + (2 + nxt) * CHK + (uint32_t)(tid + i * 256) * 16,
                     bsrc + (tid + i * 256) * 4);
            asm volatile("cp.async.commit_group;" ::: "memory");
            // A chunk kc+1 into registers
            const float* An = ((kc + 1) < 4) ? agg : X;
            int klocal = ((kc + 1) & 3) * 32;
#pragma unroll
            for (int i = 0; i < 4; i++) {
                int gr = row0 + st_row[i];
                va[i] = make_float4(0.f, 0.f, 0.f, 0.f);
                if (gr < M)
                    va[i] = *(const float4*)(An + (size_t)gr * DD + klocal
                                             + st_c4[i] * 4);
            }
        }

        // ---- MMAs on current buffers ----
        uint32_t aB = sbase + cur * CHK;
        uint32_t bB = sbase + (2 + cur) * CHK;
#pragma unroll
        for (int ks = 0; ks < 4; ks++) {
            uint32_t a[2][4], b[4][4];
            uint32_t ta = ((uint32_t)(ks * 32) + aseg) ^ aswz;
#pragma unroll
            for (int mi = 0; mi < 2; mi++)
                ldsm4(a[mi], aB + aoff + (uint32_t)mi * 2048 + ta);
            uint32_t tb = ((uint32_t)(ks * 32) + bseg) ^ bswz;
#pragma unroll
            for (int pi = 0; pi < 4; pi++)
                ldsm4(b[pi], bB + boff + (uint32_t)pi * 2048 + tb);
#pragma unroll
            for (int mi = 0; mi < 2; mi++)
#pragma unroll
                for (int pi = 0; pi < 4; pi++) {
                    mma_tf32(acc[mi][pi * 2 + 0], a[mi], &b[pi][0]);
                    mma_tf32(acc[mi][pi * 2 + 1], a[mi], &b[pi][2]);
                }
        }

        if (haven) {
#pragma unroll
            for (int i = 0; i < 4; i++) {
                float4 v = va[i];
                v.x = to_tf32(v.x); v.y = to_tf32(v.y);
                v.z = to_tf32(v.z); v.w = to_tf32(v.w);
                *(float4*)(smem + nxt * CHK + st_sw[i]) = v;
            }
            asm volatile("cp.async.wait_group 0;" ::: "memory");
        }
        __syncthreads();
    }

    // ---- epilogue ----
    int g = lane >> 2, t4 = lane & 3;
#pragma unroll
    for (int mi = 0; mi < 2; mi++) {
        int r_lo = row0 + warp_m * 32 + mi * 16 + g;
        int r_hi = r_lo + 8;
#pragma unroll
        for (int ni = 0; ni < 8; ni++) {
            int col = warp_n * 64 + ni * 8 + t4 * 2;
            float b0 = __ldg(bl + col), b1 = __ldg(bl + col + 1);
            if (r_lo < M) {
                float2 o;
                o.x = fmaxf(acc[mi][ni][0] + b0, 0.f);
                o.y = fmaxf(acc[mi][ni][1] + b1, 0.f);
                *(float2*)(Y + (size_t)r_lo * DD + col) = o;
            }
            if (r_hi < M) {
                float2 o;
                o.x = fmaxf(acc[mi][ni][2] + b0, 0.f);
                o.y = fmaxf(acc[mi][ni][3] + b1, 0.f);
                *(float2*)(Y + (size_t)r_hi * DD + col) = o;
            }
        }
    }
}

// ===========================================================================
// Launch
// ===========================================================================
extern "C" void kernel_launch(void* const* d_in, const int* in_sizes, int n_in,
                              void* d_out, int out_size) {
    const float* x  = (const float*)d_in[0];
    const void*  ei = d_in[1];
    const float* Wl1 = (const float*)d_in[2];
    const float* bl1 = (const float*)d_in[3];
    const float* Wr1 = (const float*)d_in[4];
    const float* Wl2 = (const float*)d_in[5];
    const float* bl2 = (const float*)d_in[6];
    const float* Wr2 = (const float*)d_in[7];
    const float* Wl3 = (const float*)d_in[8];
    const float* bl3 = (const float*)d_in[9];
    const float* Wr3 = (const float*)d_in[10];
    float* out = (float*)d_out;

    int M = in_sizes[0] / DD;
    int E = in_sizes[1] / 2;

    float *agg, *h1, *h2, *bpre;
    int *cnt;
    cudaGetSymbolAddress((void**)&agg,  g_agg);
    cudaGetSymbolAddress((void**)&h1,   g_h1);
    cudaGetSymbolAddress((void**)&h2,   g_h2);
    cudaGetSymbolAddress((void**)&bpre, g_Bpre);
    cudaGetSymbolAddress((void**)&cnt,  g_cnt);

    cudaFuncSetAttribute(gemm_mma, cudaFuncAttributeMaxDynamicSharedMemorySize,
                         GEMM_SMEM);

    detect_kernel<<<1, 1024>>>((const unsigned int*)ei, 2 * E);
    prep_B<<<96, 256>>>(Wl1, Wr1, Wl2, Wr2, Wl3, Wr3);

    // CSR build (once per call; reused by all 3 layers)
    cudaMemsetAsync(cnt, 0, (size_t)M * sizeof(int));
    hist_kernel<<<(E + 255) / 256, 256>>>(ei, E);
    scan_kernel<<<1, 1024>>>(M);
    fill_kernel<<<(E + 255) / 256, 256>>>(ei, E);

    int ag_blocks = (M * 32 + 255) / 256;
    int gm_blocks = (M + 127) / 128;

    const float* in = x;
    float* outs[3] = { h1, h2, out };
    const float* bls[3] = { bl1, bl2, bl3 };

    for (int L = 0; L < 3; L++) {
        agg_kernel<<<ag_blocks, 256>>>(in, agg, M);
        gemm_mma<<<gm_blocks, 256, GEMM_SMEM>>>(agg, in, bpre + L * 32768,
                                                bls[L], outs[L], M);
        in = outs[L];
    }
}

// round 9
// speedup vs baseline: 2.9501x; 1.3757x over previous
#include <cuda_runtime.h>
#include <cstdint>

#define DD 128
#define MAXN 50000
#define MAXE 600000

// Scratch (no cudaMalloc allowed): device globals.
__device__ float g_agg[MAXN * DD];
__device__ float g_h1[MAXN * DD];
__device__ float g_h2[MAXN * DD];
__device__ float g_Bpre[3 * 8 * 4096];   // per layer: 8 chunks x 4096 floats (swizzled tf32 Wl||Wr)
__device__ int   g_cnt[MAXN];
__device__ int   g_off[MAXN + 1];
__device__ int   g_cur[MAXN];
__device__ int   g_srcl[MAXE];
__device__ int   g_part[64];
__device__ int   g_base[64];
__device__ int   g_is64;

__device__ __forceinline__ uint32_t sw128(uint32_t off) {
    return off ^ ((off >> 3) & 0x70);
}

__device__ __forceinline__ float to_tf32(float x) {
    float r;
    asm("cvt.rna.tf32.f32 %0, %1;" : "=f"(r) : "f"(x));
    return r;
}

// ===========================================================================
// dtype detection (int64 vs int32 edge_index)
// ===========================================================================
__global__ void detect_kernel(const unsigned int* __restrict__ ei, int nwords) {
    __shared__ unsigned int s_or;
    if (threadIdx.x == 0) s_or = 0u;
    __syncthreads();
    unsigned int v = 0u;
    int idx = 2 * (int)threadIdx.x + 1;
    if (idx < nwords) v = ei[idx];
    int idx2 = idx + 4096;
    if (idx2 < nwords) v |= ei[idx2];
    if (v) atomicOr(&s_or, v);
    __syncthreads();
    if (threadIdx.x == 0) g_is64 = (s_or == 0u) ? 1 : 0;
}

// ===========================================================================
// CSR build: histogram -> 3-phase multi-block scan -> atomic fill
// ===========================================================================
__global__ void hist_kernel(const void* __restrict__ eidx, int E) {
    int e = blockIdx.x * blockDim.x + threadIdx.x;
    if (e >= E) return;
    int dst;
    if (g_is64) dst = (int)((const long long*)eidx)[E + e];
    else        dst = ((const int*)eidx)[E + e];
    atomicAdd(&g_cnt[dst], 1);
}

// Phase 1: per-block sum of 1024 counts
__global__ void scan1_kernel(int M) {
    __shared__ int red[32];
    int i = blockIdx.x * 1024 + threadIdx.x;
    int v = (i < M) ? g_cnt[i] : 0;
#pragma unroll
    for (int d = 16; d > 0; d >>= 1)
        v += __shfl_down_sync(0xffffffffu, v, d);
    if ((threadIdx.x & 31) == 0) red[threadIdx.x >> 5] = v;
    __syncthreads();
    if (threadIdx.x < 32) {
        int s = red[threadIdx.x];
#pragma unroll
        for (int d = 16; d > 0; d >>= 1)
            s += __shfl_down_sync(0xffffffffu, s, d);
        if (threadIdx.x == 0) g_part[blockIdx.x] = s;
    }
}

// Phase 2: serial scan of block partials (<=64), write exclusive bases + total
__global__ void scan2_kernel(int nblk, int M) {
    if (threadIdx.x == 0) {
        int run = 0;
        for (int b = 0; b < nblk; b++) {
            g_base[b] = run;
            run += g_part[b];
        }
        g_off[M] = run;
    }
}

// Phase 3: Hillis-Steele inclusive scan within block + base, write off/cur
__global__ void scan3_kernel(int M) {
    __shared__ int data[1024];
    int t = threadIdx.x;
    int i = blockIdx.x * 1024 + t;
    int v = (i < M) ? g_cnt[i] : 0;
    data[t] = v;
    __syncthreads();
#pragma unroll
    for (int d = 1; d < 1024; d <<= 1) {
        int o = (t >= d) ? data[t - d] : 0;
        __syncthreads();
        data[t] += o;
        __syncthreads();
    }
    if (i < M) {
        int excl = g_base[blockIdx.x] + data[t] - v;
        g_off[i] = excl;
        g_cur[i] = excl;
    }
}

__global__ void fill_kernel(const void* __restrict__ eidx, int E) {
    int e = blockIdx.x * blockDim.x + threadIdx.x;
    if (e >= E) return;
    int src, dst;
    if (g_is64) {
        const long long* ei = (const long long*)eidx;
        src = (int)ei[e]; dst = (int)ei[E + e];
    } else {
        const int* ei = (const int*)eidx;
        src = ei[e]; dst = ei[E + e];
    }
    int pos = atomicAdd(&g_cur[dst], 1);
    g_srcl[pos] = src;
}

// ===========================================================================
// Aggregation: one warp per node; gather neighbor rows, mean, store once.
// ===========================================================================
__global__ void __launch_bounds__(256)
agg_kernel(const float* __restrict__ X, float* __restrict__ agg, int M) {
    int node = (int)((blockIdx.x * blockDim.x + threadIdx.x) >> 5);
    int lane = threadIdx.x & 31;
    if (node >= M) return;
    int s = g_off[node], e = g_off[node + 1];

    float4 v0 = make_float4(0.f, 0.f, 0.f, 0.f);
    float4 v1 = make_float4(0.f, 0.f, 0.f, 0.f);
    for (int base = s; base < e; base += 32) {
        int mysrc = (base + lane < e) ? g_srcl[base + lane] : 0;
        int n = min(32, e - base);
        int j = 0;
        for (; j + 1 < n; j += 2) {
            int s0 = __shfl_sync(0xffffffffu, mysrc, j);
            int s1 = __shfl_sync(0xffffffffu, mysrc, j + 1);
            float4 t0 = *(const float4*)(X + (size_t)s0 * DD + lane * 4);
            float4 t1 = *(const float4*)(X + (size_t)s1 * DD + lane * 4);
            v0.x += t0.x; v0.y += t0.y; v0.z += t0.z; v0.w += t0.w;
            v1.x += t1.x; v1.y += t1.y; v1.z += t1.z; v1.w += t1.w;
        }
        if (j < n) {
            int s0 = __shfl_sync(0xffffffffu, mysrc, j);
            float4 t0 = *(const float4*)(X + (size_t)s0 * DD + lane * 4);
            v0.x += t0.x; v0.y += t0.y; v0.z += t0.z; v0.w += t0.w;
        }
    }
    float inv = 1.0f / fmaxf((float)(e - s), 1.0f);
    float4 o;
    o.x = (v0.x + v1.x) * inv;
    o.y = (v0.y + v1.y) * inv;
    o.z = (v0.z + v1.z) * inv;
    o.w = (v0.w + v1.w) * inv;
    *(float4*)(agg + (size_t)node * DD + lane * 4) = o;
}

// ===========================================================================
// Weight pre-conversion (swizzled chunk-major tf32 image; see R6 notes)
// ===========================================================================
__global__ void prep_B(const float* __restrict__ Wl1, const float* __restrict__ Wr1,
                       const float* __restrict__ Wl2, const float* __restrict__ Wr2,
                       const float* __restrict__ Wl3, const float* __restrict__ Wr3) {
    int t = blockIdx.x * blockDim.x + threadIdx.x;   // 0..24575
    int layer = t >> 13;
    int rem = t & 8191;
    int chunk = rem >> 10;
    int fid = rem & 1023;
    const float* W;
    if (layer == 0) W = (chunk < 4) ? Wl1 : Wr1;
    else if (layer == 1) W = (chunk < 4) ? Wl2 : Wr2;
    else W = (chunk < 4) ? Wl3 : Wr3;
    int row = fid >> 3, c4 = fid & 7;
    float4 v = *(const float4*)(W + row * DD + (chunk & 3) * 32 + c4 * 4);
    v.x = to_tf32(v.x); v.y = to_tf32(v.y); v.z = to_tf32(v.z); v.w = to_tf32(v.w);
    uint32_t dst = (uint32_t)layer * 32768 + (uint32_t)chunk * 4096
                 + (sw128(row * 128 + c4 * 16) >> 2);
    *(float4*)(g_Bpre + dst) = v;
}

// ===========================================================================
// tf32 mma.sync fused GEMM with ldmatrix + cp.async(B) + reg-prefetch(A)
// ===========================================================================
#define CHK 16384
#define GEMM_SMEM (4 * CHK)    // A0,A1,B0,B1

__device__ __forceinline__ uint32_t smem_u32(const void* p) {
    uint32_t a;
    asm("{ .reg .u64 t; cvta.to.shared.u64 t, %1; cvt.u32.u64 %0, t; }"
        : "=r"(a) : "l"(p));
    return a;
}

__device__ __forceinline__ void ldsm4(uint32_t* r, uint32_t addr) {
    asm volatile("ldmatrix.sync.aligned.m8n8.x4.shared.b16 {%0,%1,%2,%3}, [%4];"
                 : "=r"(r[0]), "=r"(r[1]), "=r"(r[2]), "=r"(r[3]) : "r"(addr));
}

__device__ __forceinline__ void mma_tf32(float* c, const uint32_t* a,
                                         const uint32_t* b) {
    asm("mma.sync.aligned.m16n8k8.row.col.f32.tf32.tf32.f32 "
        "{%0,%1,%2,%3}, {%4,%5,%6,%7}, {%8,%9}, {%0,%1,%2,%3};"
        : "+f"(c[0]), "+f"(c[1]), "+f"(c[2]), "+f"(c[3])
        : "r"(a[0]), "r"(a[1]), "r"(a[2]), "r"(a[3]), "r"(b[0]), "r"(b[1]));
}

__device__ __forceinline__ void cp16(uint32_t dst, const void* src) {
    asm volatile("cp.async.cg.shared.global [%0], [%1], 16;"
                 :: "r"(dst), "l"(src) : "memory");
}

__global__ void __launch_bounds__(256, 2)
gemm_mma(const float* __restrict__ agg, const float* __restrict__ X,
         const float* __restrict__ Bpre, const float* __restrict__ bl,
         float* __restrict__ Y, int M)
{
    extern __shared__ char smem[];
    uint32_t sbase = smem_u32(smem);
    int tid = threadIdx.x;
    int lane = tid & 31;
    int wid = tid >> 5;
    int warp_m = wid & 3;
    int warp_n = wid >> 2;
    int row0 = blockIdx.x << 7;

    int st_row[4], st_c4[4];
    uint32_t st_sw[4];
#pragma unroll
    for (int i = 0; i < 4; i++) {
        int fid = tid + i * 256;
        st_row[i] = fid >> 3;
        st_c4[i]  = fid & 7;
        st_sw[i]  = sw128(st_row[i] * 128 + st_c4[i] * 16);
    }

    float acc[2][8][4];
#pragma unroll
    for (int mi = 0; mi < 2; mi++)
#pragma unroll
        for (int ni = 0; ni < 8; ni++)
#pragma unroll
            for (int r = 0; r < 4; r++) acc[mi][ni][r] = 0.0f;

    int lane15 = lane & 15;
    uint32_t aseg = (lane >> 4) * 16;
    int arow = warp_m * 32 + lane15;
    uint32_t aswz = (arow & 7) * 16;
    uint32_t aoff = (uint32_t)arow * 128;

    uint32_t bseg = ((lane >> 3) & 1) * 16;
    int brow = warp_n * 64 + ((lane >> 4) * 8) + (lane & 7);
    uint32_t bswz = (brow & 7) * 16;
    uint32_t boff = (uint32_t)brow * 128;

    // ---- prologue: chunk 0 ----
    {
#pragma unroll
        for (int i = 0; i < 4; i++)
            cp16(sbase + 2 * CHK + (uint32_t)(tid + i * 256) * 16,
                 Bpre + (tid + i * 256) * 4);
        asm volatile("cp.async.commit_group;" ::: "memory");
#pragma unroll
        for (int i = 0; i < 4; i++) {
            int gr = row0 + st_row[i];
            float4 v = make_float4(0.f, 0.f, 0.f, 0.f);
            if (gr < M) v = *(const float4*)(agg + (size_t)gr * DD + st_c4[i] * 4);
            v.x = to_tf32(v.x); v.y = to_tf32(v.y);
            v.z = to_tf32(v.z); v.w = to_tf32(v.w);
            *(float4*)(smem + st_sw[i]) = v;
        }
        asm volatile("cp.async.wait_group 0;" ::: "memory");
        __syncthreads();
    }

#pragma unroll
    for (int kc = 0; kc < 8; kc++) {
        int cur = kc & 1;
        int nxt = cur ^ 1;
        float4 va[4];
        const bool haven = (kc + 1) < 8;
        if (haven) {
            const float* bsrc = Bpre + (kc + 1) * 4096;
#pragma unroll
            for (int i = 0; i < 4; i++)
                cp16(sbase + (2 + nxt) * CHK + (uint32_t)(tid + i * 256) * 16,
                     bsrc + (tid + i * 256) * 4);
            asm volatile("cp.async.commit_group;" ::: "memory");
            const float* An = ((kc + 1) < 4) ? agg : X;
            int klocal = ((kc + 1) & 3) * 32;
#pragma unroll
            for (int i = 0; i < 4; i++) {
                int gr = row0 + st_row[i];
                va[i] = make_float4(0.f, 0.f, 0.f, 0.f);
                if (gr < M)
                    va[i] = *(const float4*)(An + (size_t)gr * DD + klocal
                                             + st_c4[i] * 4);
            }
        }

        uint32_t aB = sbase + cur * CHK;
        uint32_t bB = sbase + (2 + cur) * CHK;
#pragma unroll
        for (int ks = 0; ks < 4; ks++) {
            uint32_t a[2][4], b[4][4];
            uint32_t ta = ((uint32_t)(ks * 32) + aseg) ^ aswz;
#pragma unroll
            for (int mi = 0; mi < 2; mi++)
                ldsm4(a[mi], aB + aoff + (uint32_t)mi * 2048 + ta);
            uint32_t tb = ((uint32_t)(ks * 32) + bseg) ^ bswz;
#pragma unroll
            for (int pi = 0; pi < 4; pi++)
                ldsm4(b[pi], bB + boff + (uint32_t)pi * 2048 + tb);
#pragma unroll
            for (int mi = 0; mi < 2; mi++)
#pragma unroll
                for (int pi = 0; pi < 4; pi++) {
                    mma_tf32(acc[mi][pi * 2 + 0], a[mi], &b[pi][0]);
                    mma_tf32(acc[mi][pi * 2 + 1], a[mi], &b[pi][2]);
                }
        }

        if (haven) {
#pragma unroll
            for (int i = 0; i < 4; i++) {
                float4 v = va[i];
                v.x = to_tf32(v.x); v.y = to_tf32(v.y);
                v.z = to_tf32(v.z); v.w = to_tf32(v.w);
                *(float4*)(smem + nxt * CHK + st_sw[i]) = v;
            }
            asm volatile("cp.async.wait_group 0;" ::: "memory");
        }
        __syncthreads();
    }

    // ---- epilogue ----
    int g = lane >> 2, t4 = lane & 3;
#pragma unroll
    for (int mi = 0; mi < 2; mi++) {
        int r_lo = row0 + warp_m * 32 + mi * 16 + g;
        int r_hi = r_lo + 8;
#pragma unroll
        for (int ni = 0; ni < 8; ni++) {
            int col = warp_n * 64 + ni * 8 + t4 * 2;
            float b0 = __ldg(bl + col), b1 = __ldg(bl + col + 1);
            if (r_lo < M) {
                float2 o;
                o.x = fmaxf(acc[mi][ni][0] + b0, 0.f);
                o.y = fmaxf(acc[mi][ni][1] + b1, 0.f);
                *(float2*)(Y + (size_t)r_lo * DD + col) = o;
            }
            if (r_hi < M) {
                float2 o;
                o.x = fmaxf(acc[mi][ni][2] + b0, 0.f);
                o.y = fmaxf(acc[mi][ni][3] + b1, 0.f);
                *(float2*)(Y + (size_t)r_hi * DD + col) = o;
            }
        }
    }
}

// ===========================================================================
// Launch
// ===========================================================================
extern "C" void kernel_launch(void* const* d_in, const int* in_sizes, int n_in,
                              void* d_out, int out_size) {
    const float* x  = (const float*)d_in[0];
    const void*  ei = d_in[1];
    const float* Wl1 = (const float*)d_in[2];
    const float* bl1 = (const float*)d_in[3];
    const float* Wr1 = (const float*)d_in[4];
    const float* Wl2 = (const float*)d_in[5];
    const float* bl2 = (const float*)d_in[6];
    const float* Wr2 = (const float*)d_in[7];
    const float* Wl3 = (const float*)d_in[8];
    const float* bl3 = (const float*)d_in[9];
    const float* Wr3 = (const float*)d_in[10];
    float* out = (float*)d_out;

    int M = in_sizes[0] / DD;
    int E = in_sizes[1] / 2;

    float *agg, *h1, *h2, *bpre;
    int *cnt;
    cudaGetSymbolAddress((void**)&agg,  g_agg);
    cudaGetSymbolAddress((void**)&h1,   g_h1);
    cudaGetSymbolAddress((void**)&h2,   g_h2);
    cudaGetSymbolAddress((void**)&bpre, g_Bpre);
    cudaGetSymbolAddress((void**)&cnt,  g_cnt);

    cudaFuncSetAttribute(gemm_mma, cudaFuncAttributeMaxDynamicSharedMemorySize,
                         GEMM_SMEM);

    detect_kernel<<<1, 1024>>>((const unsigned int*)ei, 2 * E);
    prep_B<<<96, 256>>>(Wl1, Wr1, Wl2, Wr2, Wl3, Wr3);

    // CSR build (once per call; reused by all 3 layers)
    cudaMemsetAsync(cnt, 0, (size_t)M * sizeof(int));
    hist_kernel<<<(E + 255) / 256, 256>>>(ei, E);
    int nblk = (M + 1023) / 1024;
    scan1_kernel<<<nblk, 1024>>>(M);
    scan2_kernel<<<1, 32>>>(nblk, M);
    scan3_kernel<<<nblk, 1024>>>(M);
    fill_kernel<<<(E + 255) / 256, 256>>>(ei, E);

    int ag_blocks = (M * 32 + 255) / 256;
    int gm_blocks = (M + 127) / 128;

    const float* in = x;
    float* outs[3] = { h1, h2, out };
    const float* bls[3] = { bl1, bl2, bl3 };

    for (int L = 0; L < 3; L++) {
        agg_kernel<<<ag_blocks, 256>>>(in, agg, M);
        gemm_mma<<<gm_blocks, 256, GEMM_SMEM>>>(agg, in, bpre + L * 32768,
                                                bls[L], outs[L], M);
        in = outs[L];
    }
}

// round 10
// speedup vs baseline: 2.9521x; 1.0007x over previous
#include <cuda_runtime.h>
#include <cstdint>

#define DD 128
#define MAXN 50000
#define MAXE 600000

// Scratch (no cudaMalloc allowed): device globals.
__device__ float g_agg[MAXN * DD];
__device__ float g_h1[MAXN * DD];
__device__ float g_h2[MAXN * DD];
__device__ float g_Bpre[3 * 8 * 4096];   // per layer: 8 chunks x 4096 floats (swizzled tf32 Wl||Wr)
__device__ int   g_cnt[MAXN];
__device__ int   g_off[MAXN + 1];
__device__ int   g_cur[MAXN];
__device__ int   g_srcl[MAXE];
__device__ int   g_part[64];
__device__ int   g_base[64];
__device__ int   g_is64;

__device__ __forceinline__ uint32_t sw128(uint32_t off) {
    return off ^ ((off >> 3) & 0x70);
}

__device__ __forceinline__ float to_tf32(float x) {
    float r;
    asm("cvt.rna.tf32.f32 %0, %1;" : "=f"(r) : "f"(x));
    return r;
}

// ===========================================================================
// dtype detection (int64 vs int32 edge_index)
// ===========================================================================
__global__ void detect_kernel(const unsigned int* __restrict__ ei, int nwords) {
    __shared__ unsigned int s_or;
    if (threadIdx.x == 0) s_or = 0u;
    __syncthreads();
    unsigned int v = 0u;
    int idx = 2 * (int)threadIdx.x + 1;
    if (idx < nwords) v = ei[idx];
    int idx2 = idx + 4096;
    if (idx2 < nwords) v |= ei[idx2];
    if (v) atomicOr(&s_or, v);
    __syncthreads();
    if (threadIdx.x == 0) g_is64 = (s_or == 0u) ? 1 : 0;
}

// ===========================================================================
// CSR build: histogram -> 3-phase multi-block scan -> atomic fill
// 4 edges per thread for MLP (these kernels are latency-bound, not BW-bound).
// ===========================================================================
__global__ void hist_kernel(const void* __restrict__ eidx, int E) {
    int e0 = (blockIdx.x * blockDim.x + threadIdx.x) * 4;
    if (e0 >= E) return;
    int n = min(4, E - e0);
    int d[4];
    if (g_is64) {
        const long long* ei = (const long long*)eidx + E;
#pragma unroll
        for (int j = 0; j < 4; j++) if (j < n) d[j] = (int)ei[e0 + j];
    } else {
        const int* ei = (const int*)eidx + E;
#pragma unroll
        for (int j = 0; j < 4; j++) if (j < n) d[j] = ei[e0 + j];
    }
#pragma unroll
    for (int j = 0; j < 4; j++) if (j < n) atomicAdd(&g_cnt[d[j]], 1);
}

// Phase 1: per-block sum of 1024 counts
__global__ void scan1_kernel(int M) {
    __shared__ int red[32];
    int i = blockIdx.x * 1024 + threadIdx.x;
    int v = (i < M) ? g_cnt[i] : 0;
#pragma unroll
    for (int d = 16; d > 0; d >>= 1)
        v += __shfl_down_sync(0xffffffffu, v, d);
    if ((threadIdx.x & 31) == 0) red[threadIdx.x >> 5] = v;
    __syncthreads();
    if (threadIdx.x < 32) {
        int s = red[threadIdx.x];
#pragma unroll
        for (int d = 16; d > 0; d >>= 1)
            s += __shfl_down_sync(0xffffffffu, s, d);
        if (threadIdx.x == 0) g_part[blockIdx.x] = s;
    }
}

// Phase 2: serial scan of block partials (<=64), write exclusive bases + total
__global__ void scan2_kernel(int nblk, int M) {
    if (threadIdx.x == 0) {
        int run = 0;
        for (int b = 0; b < nblk; b++) {
            g_base[b] = run;
            run += g_part[b];
        }
        g_off[M] = run;
    }
}

// Phase 3: Hillis-Steele inclusive scan within block + base, write off/cur
__global__ void scan3_kernel(int M) {
    __shared__ int data[1024];
    int t = threadIdx.x;
    int i = blockIdx.x * 1024 + t;
    int v = (i < M) ? g_cnt[i] : 0;
    data[t] = v;
    __syncthreads();
#pragma unroll
    for (int d = 1; d < 1024; d <<= 1) {
        int o = (t >= d) ? data[t - d] : 0;
        __syncthreads();
        data[t] += o;
        __syncthreads();
    }
    if (i < M) {
        int excl = g_base[blockIdx.x] + data[t] - v;
        g_off[i] = excl;
        g_cur[i] = excl;
    }
}

__global__ void fill_kernel(const void* __restrict__ eidx, int E) {
    int e0 = (blockIdx.x * blockDim.x + threadIdx.x) * 4;
    if (e0 >= E) return;
    int n = min(4, E - e0);
    int s[4], d[4];
    if (g_is64) {
        const long long* ei = (const long long*)eidx;
#pragma unroll
        for (int j = 0; j < 4; j++)
            if (j < n) { s[j] = (int)ei[e0 + j]; d[j] = (int)ei[E + e0 + j]; }
    } else {
        const int* ei = (const int*)eidx;
#pragma unroll
        for (int j = 0; j < 4; j++)
            if (j < n) { s[j] = ei[e0 + j]; d[j] = ei[E + e0 + j]; }
    }
    int pos[4];
#pragma unroll
    for (int j = 0; j < 4; j++) if (j < n) pos[j] = atomicAdd(&g_cur[d[j]], 1);
#pragma unroll
    for (int j = 0; j < 4; j++) if (j < n) g_srcl[pos[j]] = s[j];
}

// ===========================================================================
// Aggregation: one warp per node; gather neighbor rows, mean, store once.
// ===========================================================================
__global__ void __launch_bounds__(256)
agg_kernel(const float* __restrict__ X, float* __restrict__ agg, int M) {
    int node = (int)((blockIdx.x * blockDim.x + threadIdx.x) >> 5);
    int lane = threadIdx.x & 31;
    if (node >= M) return;
    int s = g_off[node], e = g_off[node + 1];

    float4 v0 = make_float4(0.f, 0.f, 0.f, 0.f);
    float4 v1 = make_float4(0.f, 0.f, 0.f, 0.f);
    for (int base = s; base < e; base += 32) {
        int mysrc = (base + lane < e) ? g_srcl[base + lane] : 0;
        int n = min(32, e - base);
        int j = 0;
        for (; j + 1 < n; j += 2) {
            int s0 = __shfl_sync(0xffffffffu, mysrc, j);
            int s1 = __shfl_sync(0xffffffffu, mysrc, j + 1);
            float4 t0 = *(const float4*)(X + (size_t)s0 * DD + lane * 4);
            float4 t1 = *(const float4*)(X + (size_t)s1 * DD + lane * 4);
            v0.x += t0.x; v0.y += t0.y; v0.z += t0.z; v0.w += t0.w;
            v1.x += t1.x; v1.y += t1.y; v1.z += t1.z; v1.w += t1.w;
        }
        if (j < n) {
            int s0 = __shfl_sync(0xffffffffu, mysrc, j);
            float4 t0 = *(const float4*)(X + (size_t)s0 * DD + lane * 4);
            v0.x += t0.x; v0.y += t0.y; v0.z += t0.z; v0.w += t0.w;
        }
    }
    float inv = 1.0f / fmaxf((float)(e - s), 1.0f);
    float4 o;
    o.x = (v0.x + v1.x) * inv;
    o.y = (v0.y + v1.y) * inv;
    o.z = (v0.z + v1.z) * inv;
    o.w = (v0.w + v1.w) * inv;
    *(float4*)(agg + (size_t)node * DD + lane * 4) = o;
}

// ===========================================================================
// Weight pre-conversion (swizzled chunk-major tf32 image; see R6 notes)
// ===========================================================================
__global__ void prep_B(const float* __restrict__ Wl1, const float* __restrict__ Wr1,
                       const float* __restrict__ Wl2, const float* __restrict__ Wr2,
                       const float* __restrict__ Wl3, const float* __restrict__ Wr3) {
    int t = blockIdx.x * blockDim.x + threadIdx.x;   // 0..24575
    int layer = t >> 13;
    int rem = t & 8191;
    int chunk = rem >> 10;
    int fid = rem & 1023;
    const float* W;
    if (layer == 0) W = (chunk < 4) ? Wl1 : Wr1;
    else if (layer == 1) W = (chunk < 4) ? Wl2 : Wr2;
    else W = (chunk < 4) ? Wl3 : Wr3;
    int row = fid >> 3, c4 = fid & 7;
    float4 v = *(const float4*)(W + row * DD + (chunk & 3) * 32 + c4 * 4);
    v.x = to_tf32(v.x); v.y = to_tf32(v.y); v.z = to_tf32(v.z); v.w = to_tf32(v.w);
    uint32_t dst = (uint32_t)layer * 32768 + (uint32_t)chunk * 4096
                 + (sw128(row * 128 + c4 * 16) >> 2);
    *(float4*)(g_Bpre + dst) = v;
}

// ===========================================================================
// tf32 mma.sync fused GEMM with ldmatrix + cp.async(B) + reg-prefetch(A)
// CTA tile 64 rows x 128 cols, 128 threads, occ 4 -> 782 CTAs over 592 slots
// (was 391 over 296: same work, finer makespan granularity).
// ===========================================================================
#define ACHK 8192                 // A chunk: 64 rows x 128B
#define BCHK 16384                // B chunk: 128 rows x 128B
#define OFFB 16384                // after A0,A1
#define GEMM_SMEM (2 * ACHK + 2 * BCHK)   // 49152

__device__ __forceinline__ uint32_t smem_u32(const void* p) {
    uint32_t a;
    asm("{ .reg .u64 t; cvta.to.shared.u64 t, %1; cvt.u32.u64 %0, t; }"
        : "=r"(a) : "l"(p));
    return a;
}

__device__ __forceinline__ void ldsm4(uint32_t* r, uint32_t addr) {
    asm volatile("ldmatrix.sync.aligned.m8n8.x4.shared.b16 {%0,%1,%2,%3}, [%4];"
                 : "=r"(r[0]), "=r"(r[1]), "=r"(r[2]), "=r"(r[3]) : "r"(addr));
}

__device__ __forceinline__ void mma_tf32(float* c, const uint32_t* a,
                                         const uint32_t* b) {
    asm("mma.sync.aligned.m16n8k8.row.col.f32.tf32.tf32.f32 "
        "{%0,%1,%2,%3}, {%4,%5,%6,%7}, {%8,%9}, {%0,%1,%2,%3};"
        : "+f"(c[0]), "+f"(c[1]), "+f"(c[2]), "+f"(c[3])
        : "r"(a[0]), "r"(a[1]), "r"(a[2]), "r"(a[3]), "r"(b[0]), "r"(b[1]));
}

__device__ __forceinline__ void cp16(uint32_t dst, const void* src) {
    asm volatile("cp.async.cg.shared.global [%0], [%1], 16;"
                 :: "r"(dst), "l"(src) : "memory");
}

__global__ void __launch_bounds__(128, 4)
gemm_mma(const float* __restrict__ agg, const float* __restrict__ X,
         const float* __restrict__ Bpre, const float* __restrict__ bl,
         float* __restrict__ Y, int M)
{
    extern __shared__ char smem[];
    uint32_t sbase = smem_u32(smem);
    int tid = threadIdx.x;
    int lane = tid & 31;
    int wid = tid >> 5;
    int warp_m = wid & 1;     // row group of 32 (within 64)
    int warp_n = wid >> 1;    // col group of 64 (within 128)
    int row0 = blockIdx.x << 6;

    // A staging geometry: 64 rows x 32 floats = 512 float4 over 128 threads
    int st_row[4], st_c4[4];
    uint32_t st_sw[4];
#pragma unroll
    for (int i = 0; i < 4; i++) {
        int fid = tid + i * 128;       // 0..511
        st_row[i] = fid >> 3;          // 0..63
        st_c4[i]  = fid & 7;
        st_sw[i]  = sw128(st_row[i] * 128 + st_c4[i] * 16);
    }

    float acc[2][8][4];
#pragma unroll
    for (int mi = 0; mi < 2; mi++)
#pragma unroll
        for (int ni = 0; ni < 8; ni++)
#pragma unroll
            for (int r = 0; r < 4; r++) acc[mi][ni][r] = 0.0f;

    int lane15 = lane & 15;
    uint32_t aseg = (lane >> 4) * 16;
    int arow = warp_m * 32 + lane15;            // 0..47 (<64)
    uint32_t aswz = (arow & 7) * 16;
    uint32_t aoff = (uint32_t)arow * 128;

    uint32_t bseg = ((lane >> 3) & 1) * 16;
    int brow = warp_n * 64 + ((lane >> 4) * 8) + (lane & 7);
    uint32_t bswz = (brow & 7) * 16;
    uint32_t boff = (uint32_t)brow * 128;

    // ---- prologue: chunk 0 ----
    {
#pragma unroll
        for (int i = 0; i < 8; i++) {
            int fid = tid + i * 128;   // 0..1023
            cp16(sbase + OFFB + (uint32_t)fid * 16, Bpre + fid * 4);
        }
        asm volatile("cp.async.commit_group;" ::: "memory");
#pragma unroll
        for (int i = 0; i < 4; i++) {
            int gr = row0 + st_row[i];
            float4 v = make_float4(0.f, 0.f, 0.f, 0.f);
            if (gr < M) v = *(const float4*)(agg + (size_t)gr * DD + st_c4[i] * 4);
            v.x = to_tf32(v.x); v.y = to_tf32(v.y);
            v.z = to_tf32(v.z); v.w = to_tf32(v.w);
            *(float4*)(smem + st_sw[i]) = v;
        }
        asm volatile("cp.async.wait_group 0;" ::: "memory");
        __syncthreads();
    }

#pragma unroll
    for (int kc = 0; kc < 8; kc++) {
        int cur = kc & 1;
        int nxt = cur ^ 1;
        float4 va[4];
        const bool haven = (kc + 1) < 8;
        if (haven) {
            const float* bsrc = Bpre + (kc + 1) * 4096;
#pragma unroll
            for (int i = 0; i < 8; i++) {
                int fid = tid + i * 128;
                cp16(sbase + OFFB + (uint32_t)nxt * BCHK + (uint32_t)fid * 16,
                     bsrc + fid * 4);
            }
            asm volatile("cp.async.commit_group;" ::: "memory");
            const float* An = ((kc + 1) < 4) ? agg : X;
            int klocal = ((kc + 1) & 3) * 32;
#pragma unroll
            for (int i = 0; i < 4; i++) {
                int gr = row0 + st_row[i];
                va[i] = make_float4(0.f, 0.f, 0.f, 0.f);
                if (gr < M)
                    va[i] = *(const float4*)(An + (size_t)gr * DD + klocal
                                             + st_c4[i] * 4);
            }
        }

        uint32_t aB = sbase + (uint32_t)cur * ACHK;
        uint32_t bB = sbase + OFFB + (uint32_t)cur * BCHK;
#pragma unroll
        for (int ks = 0; ks < 4; ks++) {
            uint32_t a[2][4], b[4][4];
            uint32_t ta = ((uint32_t)(ks * 32) + aseg) ^ aswz;
#pragma unroll
            for (int mi = 0; mi < 2; mi++)
                ldsm4(a[mi], aB + aoff + (uint32_t)mi * 2048 + ta);
            uint32_t tb = ((uint32_t)(ks * 32) + bseg) ^ bswz;
#pragma unroll
            for (int pi = 0; pi < 4; pi++)
                ldsm4(b[pi], bB + boff + (uint32_t)pi * 2048 + tb);
#pragma unroll
            for (int mi = 0; mi < 2; mi++)
#pragma unroll
                for (int pi = 0; pi < 4; pi++) {
                    mma_tf32(acc[mi][pi * 2 + 0], a[mi], &b[pi][0]);
                    mma_tf32(acc[mi][pi * 2 + 1], a[mi], &b[pi][2]);
                }
        }

        if (haven) {
#pragma unroll
            for (int i = 0; i < 4; i++) {
                float4 v = va[i];
                v.x = to_tf32(v.x); v.y = to_tf32(v.y);
                v.z = to_tf32(v.z); v.w = to_tf32(v.w);
                *(float4*)(smem + nxt * ACHK + st_sw[i]) = v;
            }
            asm volatile("cp.async.wait_group 0;" ::: "memory");
        }
        __syncthreads();
    }

    // ---- epilogue ----
    int g = lane >> 2, t4 = lane & 3;
#pragma unroll
    for (int mi = 0; mi < 2; mi++) {
        int r_lo = row0 + warp_m * 32 + mi * 16 + g;
        int r_hi = r_lo + 8;
#pragma unroll
        for (int ni = 0; ni < 8; ni++) {
            int col = warp_n * 64 + ni * 8 + t4 * 2;
            float b0 = __ldg(bl + col), b1 = __ldg(bl + col + 1);
            if (r_lo < M) {
                float2 o;
                o.x = fmaxf(acc[mi][ni][0] + b0, 0.f);
                o.y = fmaxf(acc[mi][ni][1] + b1, 0.f);
                *(float2*)(Y + (size_t)r_lo * DD + col) = o;
            }
            if (r_hi < M) {
                float2 o;
                o.x = fmaxf(acc[mi][ni][2] + b0, 0.f);
                o.y = fmaxf(acc[mi][ni][3] + b1, 0.f);
                *(float2*)(Y + (size_t)r_hi * DD + col) = o;
            }
        }
    }
}

// ===========================================================================
// Launch
// ===========================================================================
extern "C" void kernel_launch(void* const* d_in, const int* in_sizes, int n_in,
                              void* d_out, int out_size) {
    const float* x  = (const float*)d_in[0];
    const void*  ei = d_in[1];
    const float* Wl1 = (const float*)d_in[2];
    const float* bl1 = (const float*)d_in[3];
    const float* Wr1 = (const float*)d_in[4];
    const float* Wl2 = (const float*)d_in[5];
    const float* bl2 = (const float*)d_in[6];
    const float* Wr2 = (const float*)d_in[7];
    const float* Wl3 = (const float*)d_in[8];
    const float* bl3 = (const float*)d_in[9];
    const float* Wr3 = (const float*)d_in[10];
    float* out = (float*)d_out;

    int M = in_sizes[0] / DD;
    int E = in_sizes[1] / 2;

    float *agg, *h1, *h2, *bpre;
    int *cnt;
    cudaGetSymbolAddress((void**)&agg,  g_agg);
    cudaGetSymbolAddress((void**)&h1,   g_h1);
    cudaGetSymbolAddress((void**)&h2,   g_h2);
    cudaGetSymbolAddress((void**)&bpre, g_Bpre);
    cudaGetSymbolAddress((void**)&cnt,  g_cnt);

    cudaFuncSetAttribute(gemm_mma, cudaFuncAttributeMaxDynamicSharedMemorySize,
                         GEMM_SMEM);

    detect_kernel<<<1, 1024>>>((const unsigned int*)ei, 2 * E);
    prep_B<<<96, 256>>>(Wl1, Wr1, Wl2, Wr2, Wl3, Wr3);

    // CSR build (once per call; reused by all 3 layers)
    cudaMemsetAsync(cnt, 0, (size_t)M * sizeof(int));
    int e4_blocks = (E / 4 + 255) / 256 + 1;
    hist_kernel<<<e4_blocks, 256>>>(ei, E);
    int nblk = (M + 1023) / 1024;
    scan1_kernel<<<nblk, 1024>>>(M);
    scan2_kernel<<<1, 32>>>(nblk, M);
    scan3_kernel<<<nblk, 1024>>>(M);
    fill_kernel<<<e4_blocks, 256>>>(ei, E);

    int ag_blocks = (M * 32 + 255) / 256;
    int gm_blocks = (M + 63) / 64;

    const float* in = x;
    float* outs[3] = { h1, h2, out };
    const float* bls[3] = { bl1, bl2, bl3 };

    for (int L = 0; L < 3; L++) {
        agg_kernel<<<ag_blocks, 256>>>(in, agg, M);
        gemm_mma<<<gm_blocks, 128, GEMM_SMEM>>>(agg, in, bpre + L * 32768,
                                                bls[L], outs[L], M);
        in = outs[L];
    }
}